// round 10
// baseline (speedup 1.0000x reference)
#include <cuda_runtime.h>
#include <math.h>

#define TPB 256

namespace FN {

constexpr int NE = 16;

struct __align__(16) Smem {
  float one[NE * 260];     // one-stream activations (layer0: cols0-15 = raw features)
  float two[256 * 33];     // two-stream activations, row (i*16+j), stride 33
  float wt[2 * 16 * 260];  // double-buffered weight tiles, transposed [fi][o]
  float wwt[32 * 36];      // two-stream weights transposed [f][o]
  float two4[256 * 5];     // layer-0 two features (dx,dy,dz,|d|)  } det arena alias
  float f0s[16 * 60];      // layer-0 f vectors                    } (2240 floats)
  float g1u[256], g1d[256];
  float g2u[512], g2d[512];
  float c[256];
  float bw[32];
  float xx[48], pos[12], rr[64];
  float sg[512], pw[512], eg[128];
};

__device__ __forceinline__ float ftanh(float x) {
  float ax = fabsf(x);
  float e = __expf(-2.0f * ax);
  float t = __fdividef(1.0f - e, 1.0f + e);
  return x >= 0.0f ? t : -t;
}

template<int KT>
__device__ __forceinline__ void ldg_tile(const float* __restrict__ W, int ldw, int f0, float* rg) {
  constexpr int EPT = 256 * KT / TPB;
#pragma unroll
  for (int e = 0; e < EPT; e++) {
    int idx = threadIdx.x + e * TPB;
    int o = idx / KT, fi = idx - o * KT;
    rg[e] = __ldg(W + o * ldw + f0 + fi);
  }
}
template<int KT>
__device__ __forceinline__ void sts_tile(float* buf, const float* rg) {
  constexpr int EPT = 256 * KT / TPB;
#pragma unroll
  for (int e = 0; e < EPT; e++) {
    int idx = threadIdx.x + e * TPB;
    int o = idx / KT, fi = idx - o * KT;
    buf[fi * 260 + o] = rg[e];
  }
}
__device__ __forceinline__ void ldg0(const float* __restrict__ W, int f0, float* rg) {
#pragma unroll
  for (int e = 0; e < 8; e++) {
    int idx = threadIdx.x + e * TPB;
    int o = idx >> 3, fi = idx & 7;
    int col = f0 + fi;
    rg[e] = (col < 56) ? __ldg(W + o * 56 + col) : 0.0f;
  }
}
__device__ __forceinline__ void sts0(float* buf, const float* rg) {
#pragma unroll
  for (int e = 0; e < 8; e++) {
    int idx = threadIdx.x + e * TPB;
    int o = idx >> 3, fi = idx & 7;
    buf[fi * 260 + o] = rg[e];
  }
}
template<int KT>
__device__ __forceinline__ void c_tile(const float* buf, const float* g, float& acc) {
#pragma unroll
  for (int fi = 0; fi < KT; fi++) acc += g[fi] * buf[fi * 260 + threadIdx.x];
}
template<int KT, int AS>
__device__ __forceinline__ void one_tile(const float* buf, const float* act, int ob, float* acc) {
#pragma unroll
  for (int fi = 0; fi < KT; fi++) {
    float4 w = *(const float4*)(buf + fi * 260 + ob);
    float a0 = act[0 * AS + fi], a1 = act[1 * AS + fi];
    float a2 = act[2 * AS + fi], a3 = act[3 * AS + fi];
    acc[0]  += a0 * w.x; acc[1]  += a0 * w.y; acc[2]  += a0 * w.z; acc[3]  += a0 * w.w;
    acc[4]  += a1 * w.x; acc[5]  += a1 * w.y; acc[6]  += a1 * w.z; acc[7]  += a1 * w.w;
    acc[8]  += a2 * w.x; acc[9]  += a2 * w.y; acc[10] += a2 * w.z; acc[11] += a2 * w.w;
    acc[12] += a3 * w.x; acc[13] += a3 * w.y; acc[14] += a3 * w.z; acc[15] += a3 * w.w;
  }
}

__global__ void __launch_bounds__(TPB, 2)
ferminet_kernel(const float* __restrict__ x, const float* __restrict__ nuc,
                const float* __restrict__ v0w, const float* __restrict__ v0b,
                const float* __restrict__ vw,  const float* __restrict__ vb,
                const float* __restrict__ w0w, const float* __restrict__ w0b,
                const float* __restrict__ ww,  const float* __restrict__ wb,
                const float* __restrict__ envw, const float* __restrict__ envg,
                const float* __restrict__ sigma, const float* __restrict__ pi,
                float* __restrict__ out) {
  extern __shared__ float smem_raw[];
  Smem* S = (Smem*)smem_raw;
  const int tid = threadIdx.x;
  const int b = blockIdx.x;
  const int g = tid >> 6;         // electron group (4 electrons)
  const int ob = (tid & 63) * 4;  // output base (4 outputs)

  // ---- Phase A: small tensors ----
  if (tid < 48) S->xx[tid] = x[b * 48 + tid];
  if (tid < 12) S->pos[tid] = nuc[tid];
  {
    int q = tid;                       // q = (k*8+i)*4+m, i<8; global (k*16+i)*4+m
    S->sg[q] = fabsf(sigma[q + (q >> 5) * 32]);
    S->pw[q] = pi[q + (q >> 5) * 32];
    q = tid + 256;
    S->sg[q] = fabsf(sigma[q + (q >> 5) * 32]);
    S->pw[q] = pi[q + (q >> 5) * 32];
  }
  if (tid < 128) S->eg[tid] = envg[(tid >> 3) * NE + (tid & 7)];
  __syncthreads();

  // ---- Phase B: geometry ----
  {
    int i = tid >> 4, j = tid & 15;
    float dx = S->xx[j * 3 + 0] - S->xx[i * 3 + 0];
    float dy = S->xx[j * 3 + 1] - S->xx[i * 3 + 1];
    float dz = S->xx[j * 3 + 2] - S->xx[i * 3 + 2];
    float ss = dx * dx + dy * dy + dz * dz;
    float nr = ss > 0.0f ? sqrtf(ss) : 0.0f;
    float* t4 = S->two4 + tid * 5;
    t4[0] = dx; t4[1] = dy; t4[2] = dz; t4[3] = nr;
  }
  if (tid < 64) {
    int n = tid >> 2, m = tid & 3;
    float ex = S->xx[n * 3 + 0] - S->pos[m * 3 + 0];
    float ey = S->xx[n * 3 + 1] - S->pos[m * 3 + 1];
    float ez = S->xx[n * 3 + 2] - S->pos[m * 3 + 2];
    float d = sqrtf(ex * ex + ey * ey + ez * ez);
    float* o1 = S->one + n * 260 + m * 4;
    o1[0] = ex; o1[1] = ey; o1[2] = ez; o1[3] = d;
    S->rr[n * 4 + m] = d;
  }
  __syncthreads();

  // ---- Layer 0 ----
  {
    if (tid < 32) {  // g1 means over 16-dim raw one
      int f = tid & 15; bool up = tid < 16;
      float s = 0.0f;
#pragma unroll
      for (int n = 0; n < 8; n++) s += S->one[(up ? n : n + 8) * 260 + f];
      (up ? S->g1u : S->g1d)[f] = s * 0.125f;
    }
    if (tid < 128) {  // g2 means over 4-dim two4
      int i = tid >> 3, c2 = tid & 7;
      int col = c2 & 3; bool up2 = c2 < 4;
      float s = 0.0f;
#pragma unroll
      for (int j = 0; j < 8; j++) s += S->two4[(i * NE + (up2 ? j : j + 8)) * 5 + col];
      (up2 ? S->g2u : S->g2d)[i * 32 + col] = s * 0.125f;
    }
    // stage two-stream layer-0 weights
    if (tid < 128) S->wwt[(tid & 3) * 36 + (tid >> 2)] = __ldg(w0w + tid);
    if (tid < 32) S->bw[tid] = __ldg(w0b + tid);
    __syncthreads();

    // build f0 vectors [16][60] (pad 56..59 = 0)
#pragma unroll
    for (int e = 0; e < 4; e++) {
      int idx = tid + e * TPB;
      if (idx < 960) {
        int n = idx / 60, cc = idx - n * 60;
        float v;
        if (cc < 16)      v = S->one[n * 260 + cc];
        else if (cc < 32) v = S->g1u[cc - 16];
        else if (cc < 48) v = S->g1d[cc - 32];
        else if (cc < 52) v = S->g2u[n * 32 + (cc - 48)];
        else if (cc < 56) v = S->g2d[n * 32 + (cc - 52)];
        else              v = 0.0f;
        S->f0s[idx] = v;
      }
    }

    float acc1[16];
#pragma unroll
    for (int q = 0; q < 16; q++) acc1[q] = 0.0f;
    {
      float rg[8];
      ldg0(v0w, 0, rg);
      for (int T = 0; T < 7; T++) {
        float* cur = S->wt + (T & 1) * 4160;
        sts0(cur, rg);
        __syncthreads();
        if (T + 1 < 7) ldg0(v0w, (T + 1) * 8, rg);
        one_tile<8, 60>(cur, S->f0s + (g * 4) * 60 + T * 8, ob, acc1);
      }
    }
    {
      float4 bb = *(const float4*)(v0b + ob);
#pragma unroll
      for (int r = 0; r < 4; r++) {
        int n = g * 4 + r;
        float4 v;
        v.x = ftanh(acc1[r * 4 + 0] + bb.x);
        v.y = ftanh(acc1[r * 4 + 1] + bb.y);
        v.z = ftanh(acc1[r * 4 + 2] + bb.z);
        v.w = ftanh(acc1[r * 4 + 3] + bb.w);
        *(float4*)(S->one + n * 260 + ob) = v;
      }
    }
    // two-stream layer 0 (K=4)
    {
      float acc2[32];
#pragma unroll
      for (int q = 0; q < 32; q++) acc2[q] = 0.0f;
      const float* a4 = S->two4 + tid * 5;
#pragma unroll
      for (int f = 0; f < 4; f++) {
        float av = a4[f];
#pragma unroll
        for (int o4 = 0; o4 < 8; o4++) {
          float4 w = *(const float4*)(S->wwt + f * 36 + o4 * 4);
          acc2[o4 * 4 + 0] += av * w.x; acc2[o4 * 4 + 1] += av * w.y;
          acc2[o4 * 4 + 2] += av * w.z; acc2[o4 * 4 + 3] += av * w.w;
        }
      }
#pragma unroll
      for (int o = 0; o < 32; o++) S->two[tid * 33 + o] = ftanh(acc2[o] + S->bw[o]);
    }
  }

  // ---- Layers 1..3 ----
  for (int l = 1; l < 4; l++) {
    __syncthreads();
    const float* Wv = vw + (l - 1) * (256 * 832);
    // g means
    {
      float su = 0.0f, sd = 0.0f;
#pragma unroll
      for (int n = 0; n < 8; n++) {
        su += S->one[n * 260 + tid];
        sd += S->one[(n + 8) * 260 + tid];
      }
      S->g1u[tid] = su * 0.125f;
      S->g1d[tid] = sd * 0.125f;
#pragma unroll
      for (int rep = 0; rep < 2; rep++) {
        int idx = tid + rep * TPB;
        int i = idx >> 5, o = idx & 31;
        float a = 0.0f, bb = 0.0f;
#pragma unroll
        for (int j = 0; j < 8; j++) {
          a  += S->two[(i * NE + j) * 33 + o];
          bb += S->two[(i * NE + j + 8) * 33 + o];
        }
        S->g2u[i * 32 + o] = a * 0.125f;
        S->g2d[i * 32 + o] = bb * 0.125f;
      }
    }
    // stage this layer's two-stream weights (read much later; tile bars order it)
    {
      const float* Ww = ww + (l - 1) * 1024;
#pragma unroll
      for (int e = 0; e < 4; e++) {
        int idx = tid + e * TPB;
        S->wwt[(idx & 31) * 36 + (idx >> 5)] = __ldg(Ww + idx);
      }
      if (tid < 32) S->bw[tid] = __ldg(wb + (l - 1) * 32 + tid);
    }

    // row-constant projection c[o] over g1 cols 256..767
    float cacc = __ldg(vb + (l - 1) * 256 + tid);
    {
      float rg[16];
      ldg_tile<16>(Wv, 832, 256, rg);
      for (int T = 0; T < 32; T++) {
        float* cur = S->wt + (T & 1) * 4160;
        sts_tile<16>(cur, rg);
        __syncthreads();
        if (T + 1 < 32) ldg_tile<16>(Wv, 832, 256 + (T + 1) * 16, rg);
        const float* gv = (T < 16) ? S->g1u + T * 16 : S->g1d + (T - 16) * 16;
        c_tile<16>(cur, gv, cacc);
      }
    }
    S->c[tid] = cacc;

    // electron GEMM: cols 0..255 (one) + 768..831 (g2)
    float acc1[16];
#pragma unroll
    for (int q = 0; q < 16; q++) acc1[q] = 0.0f;
    const float* actb = S->one + (g * 4) * 260;
    {
      float rg[16];
      ldg_tile<16>(Wv, 832, 0, rg);
      for (int T = 0; T < 20; T++) {
        float* cur = S->wt + (T & 1) * 4160;
        sts_tile<16>(cur, rg);
        __syncthreads();
        int Tn = T + 1;
        if (Tn < 20) {
          int f0 = (Tn < 16) ? Tn * 16 : 768 + (Tn - 16) * 16;
          ldg_tile<16>(Wv, 832, f0, rg);
        }
        if (T < 16) {
          one_tile<16, 260>(cur, actb + T * 16, ob, acc1);
        } else {
          const float* a2 = ((T < 18) ? S->g2u : S->g2d) + (g * 4) * 32 + ((T & 1) ? 16 : 0);
          one_tile<16, 32>(cur, a2, ob, acc1);
        }
      }
    }
    // writeback with residual
    {
      float4 cc4 = *(const float4*)(S->c + ob);
#pragma unroll
      for (int r = 0; r < 4; r++) {
        int n = g * 4 + r;
        float4 old = *(const float4*)(S->one + n * 260 + ob);
        float4 v;
        v.x = ftanh(acc1[r * 4 + 0] + cc4.x) + old.x;
        v.y = ftanh(acc1[r * 4 + 1] + cc4.y) + old.y;
        v.z = ftanh(acc1[r * 4 + 2] + cc4.z) + old.z;
        v.w = ftanh(acc1[r * 4 + 3] + cc4.w) + old.w;
        *(float4*)(S->one + n * 260 + ob) = v;
      }
    }
    // two-stream GEMM (K=32) + residual
    {
      float acc2[32];
#pragma unroll
      for (int q = 0; q < 32; q++) acc2[q] = 0.0f;
      float* arow = S->two + tid * 33;
#pragma unroll
      for (int f = 0; f < 32; f++) {
        float av = arow[f];
#pragma unroll
        for (int o4 = 0; o4 < 8; o4++) {
          float4 w = *(const float4*)(S->wwt + f * 36 + o4 * 4);
          acc2[o4 * 4 + 0] += av * w.x; acc2[o4 * 4 + 1] += av * w.y;
          acc2[o4 * 4 + 2] += av * w.z; acc2[o4 * 4 + 3] += av * w.w;
        }
      }
#pragma unroll
      for (int o = 0; o < 32; o++) arow[o] = ftanh(acc2[o] + S->bw[o]) + arow[o];
    }
  }

  __syncthreads();

  // ---- Envelope / orbitals ----
  float* D = S->two4;  // det arena aliases two4+f0s (both dead)
  {
    int k = tid >> 4, i = (tid >> 1) & 7, jh = tid & 1;
    const float* wrow = envw + (k * 16 + i) * 256;
    float acc[8];
#pragma unroll
    for (int j = 0; j < 8; j++) acc[j] = 0.0f;
    for (int f4 = 0; f4 < 64; f4++) {
      float4 w = __ldg((const float4*)(wrow + f4 * 4));
#pragma unroll
      for (int j = 0; j < 8; j++) {
        float4 a = *(const float4*)(S->one + (jh * 8 + j) * 260 + f4 * 4);
        acc[j] += w.x * a.x + w.y * a.y + w.z * a.z + w.w * a.w;
      }
    }
    float lg = 256.0f * S->eg[k * 8 + i];
    int si = (k * 8 + i) * 4;
    float p0 = S->pw[si], p1 = S->pw[si + 1], p2 = S->pw[si + 2], p3 = S->pw[si + 3];
    float s0 = S->sg[si], s1 = S->sg[si + 1], s2 = S->sg[si + 2], s3 = S->sg[si + 3];
#pragma unroll
    for (int j = 0; j < 8; j++) {
      int col = jh * 8 + j;
      const float* rrow = S->rr + col * 4;
      float env = p0 * __expf(-s0 * rrow[0]) + p1 * __expf(-s1 * rrow[1]) +
                  p2 * __expf(-s2 * rrow[2]) + p3 * __expf(-s3 * rrow[3]);
      D[(jh * 16 + k) * 65 + i * 8 + j] = (acc[j] + lg) * env;
    }
  }
  __syncthreads();

  // ---- Determinants (32 matrices 8x8, pivoted LU) ----
  float* dets = D + 2080;
  float* prods = D + 2112;
  if (tid < 32) {
    float* A = D + tid * 65;
    float dv = 1.0f;
    for (int cph = 0; cph < 8; cph++) {
      int p = cph; float mx = fabsf(A[cph * 8 + cph]);
      for (int r = cph + 1; r < 8; r++) {
        float fv = fabsf(A[r * 8 + cph]);
        if (fv > mx) { mx = fv; p = r; }
      }
      if (mx == 0.0f) { dv = 0.0f; break; }
      if (p != cph) {
#pragma unroll
        for (int cc = 0; cc < 8; cc++) {
          float t = A[cph * 8 + cc]; A[cph * 8 + cc] = A[p * 8 + cc]; A[p * 8 + cc] = t;
        }
        dv = -dv;
      }
      float piv = A[cph * 8 + cph];
      dv *= piv;
      float inv = 1.0f / piv;
      for (int r = cph + 1; r < 8; r++) {
        float m = A[r * 8 + cph] * inv;
        for (int cc = cph + 1; cc < 8; cc++) A[r * 8 + cc] -= m * A[cph * 8 + cc];
      }
    }
    dets[tid] = dv;
  }
  __syncthreads();
  if (tid < 16) prods[tid] = dets[tid] * dets[16 + tid];
  __syncthreads();
  if (tid == 0) {
    float s = 0.0f;
#pragma unroll
    for (int k = 0; k < 16; k++) s += prods[k];
    out[b] = s;
  }
}

}  // namespace FN

extern "C" void kernel_launch(void* const* d_in, const int* in_sizes, int n_in,
                              void* d_out, int out_size) {
  const float* x    = (const float*)d_in[0];
  const float* nuc  = (const float*)d_in[1];
  const float* v0w  = (const float*)d_in[2];
  const float* v0b  = (const float*)d_in[3];
  const float* vw   = (const float*)d_in[4];
  const float* vb   = (const float*)d_in[5];
  const float* w0w  = (const float*)d_in[6];
  const float* w0b  = (const float*)d_in[7];
  const float* ww   = (const float*)d_in[8];
  const float* wb   = (const float*)d_in[9];
  const float* envw = (const float*)d_in[10];
  const float* envg = (const float*)d_in[11];
  const float* sig  = (const float*)d_in[12];
  const float* pi   = (const float*)d_in[13];
  float* out = (float*)d_out;

  int B = in_sizes[0] / 48;
  int smem = (int)sizeof(FN::Smem);
  cudaFuncSetAttribute(FN::ferminet_kernel, cudaFuncAttributeMaxDynamicSharedMemorySize, smem);
  FN::ferminet_kernel<<<B, TPB, smem>>>(x, nuc, v0w, v0b, vw, vb, w0w, w0b, ww, wb,
                                        envw, envg, sig, pi, out);
}